// round 7
// baseline (speedup 1.0000x reference)
#include <cuda_runtime.h>
#include <math.h>

#define N_NODES_ 100000
#define N_EDGES_ 500000
#define HID_ 128
#define NIN_ 16
#define SCAN_B 1024
#define NBLK_ ((N_NODES_ + SCAN_B - 1) / SCAN_B)   // 98
#define NODE_BLKS ((N_NODES_ + 127) / 128)         // 782
#define SSTR 132                                   // smem row stride (floats), conflict-free
#define SMEM_TC (128 * SSTR * 4)                   // 67584 B dynamic smem

typedef unsigned int uint32;

// ---- static scratch (no allocations allowed) ----
__device__ float g_h  [N_NODES_ * HID_];
__device__ float g_hn [N_NODES_ * HID_];
__device__ float g_P  [N_NODES_ * 2 * HID_];
__device__ int   g_deg   [N_NODES_];
__device__ int   g_rowptr[N_NODES_ + 1];
__device__ int   g_cursor[N_NODES_];
__device__ int   g_csrc  [N_EDGES_];
__device__ int   g_ceid  [N_EDGES_];
__device__ float g_cea   [N_EDGES_];

// ---- fragment-ordered TF32 hi/lo weights: [kstep][ntile][lane] = {bhi0,bhi1,blo0,blo1}
#define WF_W10 0                 // K=16 : 2*16*32   = 1024
#define WF_W20 1024              // K=128: 16*16*32  = 8192
#define WF_W1  9216              // 4 x 8192
#define WF_W2  41984             // 4 x 8192
#define WF_WPA 74752             // Wp1 rows 0..127
#define WF_WPB 82944             // Wp1 rows 128..255
#define WF_TOTAL 91136
__device__ uint4 g_WF[WF_TOTAL];

__device__ __forceinline__ float4 ld4(const float* p) { return *reinterpret_cast<const float4*>(p); }
__device__ __forceinline__ void st4(float* p, float4 v) { *reinterpret_cast<float4*>(p) = v; }
__device__ __forceinline__ float eluf(float x) { return x > 0.f ? x : expm1f(x); }

// ---- tf32 helpers ----
__device__ __forceinline__ uint32 tf32_hi(float f) {
    uint32 r; asm("cvt.rna.tf32.f32 %0, %1;" : "=r"(r) : "f"(f)); return r;
}
__device__ __forceinline__ uint32 tf32_lo(float f, uint32 hi) {
    return tf32_hi(f - __uint_as_float(hi));
}

// D += A(tf32) * B(tf32), m16n8k8
__device__ __forceinline__ void mma8(float c[4], uint32 a0, uint32 a1, uint32 a2, uint32 a3,
                                     uint32 b0, uint32 b1)
{
    asm volatile(
        "mma.sync.aligned.m16n8k8.row.col.f32.tf32.tf32.f32 "
        "{%0,%1,%2,%3}, {%4,%5,%6,%7}, {%8,%9}, {%0,%1,%2,%3};"
        : "+f"(c[0]), "+f"(c[1]), "+f"(c[2]), "+f"(c[3])
        : "r"(a0), "r"(a1), "r"(a2), "r"(a3), "r"(b0), "r"(b1));
}

// ---------------------------------------------------------------------------
// One MMA phase: warp computes C[16 rows x 128 cols] = Zw @ W (3xTF32 split).
// ---------------------------------------------------------------------------
template <int KSTEPS>
__device__ __forceinline__ void mma_phase(const float* Zw, const uint4* __restrict__ WF,
                                          int lane, float c[16][4])
{
    int g = lane >> 2, t = lane & 3;
    #pragma unroll
    for (int nt = 0; nt < 16; nt++) { c[nt][0] = 0.f; c[nt][1] = 0.f; c[nt][2] = 0.f; c[nt][3] = 0.f; }

    #pragma unroll 1
    for (int ks = 0; ks < KSTEPS; ks++) {
        float z0 = Zw[g * SSTR + ks * 8 + t];
        float z1 = Zw[(g + 8) * SSTR + ks * 8 + t];
        float z2 = Zw[g * SSTR + ks * 8 + t + 4];
        float z3 = Zw[(g + 8) * SSTR + ks * 8 + t + 4];
        uint32 ah0 = tf32_hi(z0), ah1 = tf32_hi(z1), ah2 = tf32_hi(z2), ah3 = tf32_hi(z3);
        uint32 al0 = tf32_lo(z0, ah0), al1 = tf32_lo(z1, ah1);
        uint32 al2 = tf32_lo(z2, ah2), al3 = tf32_lo(z3, ah3);
        const uint4* wrow = &WF[ks * 16 * 32 + lane];
        #pragma unroll
        for (int nt = 0; nt < 16; nt++) {
            uint4 wf = wrow[nt * 32];
            mma8(c[nt], ah0, ah1, ah2, ah3, wf.x, wf.y);   // Ahi*Bhi
            mma8(c[nt], al0, al1, al2, al3, wf.x, wf.y);   // Alo*Bhi
            mma8(c[nt], ah0, ah1, ah2, ah3, wf.z, wf.w);   // Ahi*Blo
        }
    }
}

// ---------------------------------------------------------------------------
// Weight fragment prep (once per launch)
// ---------------------------------------------------------------------------
__global__ void k_wfrag(const float* __restrict__ W10, const float* __restrict__ W20,
                        const float* __restrict__ W1s, const float* __restrict__ W2s,
                        const float* __restrict__ Wp1)
{
    int i = blockIdx.x * 256 + threadIdx.x;
    if (i >= WF_TOTAL) return;
    const float* W; int idx;
    if (i < 1024)        { W = W10; idx = i; }
    else if (i < 9216)   { W = W20; idx = i - 1024; }
    else if (i < 41984)  { int j = i - 9216;  W = W1s + (j >> 13) * 16384; idx = j & 8191; }
    else if (i < 74752)  { int j = i - 41984; W = W2s + (j >> 13) * 16384; idx = j & 8191; }
    else if (i < 82944)  { W = Wp1;           idx = i - 74752; }
    else                 { W = Wp1 + 16384;   idx = i - 82944; }
    int lane = idx & 31, nt = (idx >> 5) & 15, ks = idx >> 9;
    int k0 = ks * 8 + (lane & 3);
    int n  = nt * 8 + (lane >> 2);
    float w0 = W[k0 * 128 + n];
    float w1 = W[(k0 + 4) * 128 + n];
    uint32 h0 = tf32_hi(w0), h1 = tf32_hi(w1);
    g_WF[i] = make_uint4(h0, h1, tf32_lo(w0, h0), tf32_lo(w1, h1));
}

// ---------------------------------------------------------------------------
// CSR build
// ---------------------------------------------------------------------------
__global__ void k_hist(const int* __restrict__ ei) {
    int e = blockIdx.x * blockDim.x + threadIdx.x;
    if (e < N_EDGES_) atomicAdd(&g_deg[ei[N_EDGES_ + e]], 1);
}

// Single-block exclusive scan over g_deg -> g_rowptr/g_cursor
__global__ void k_scan1() {
    __shared__ int wsum[32];
    __shared__ int carry, total;
    int t = threadIdx.x;
    int wid = t >> 5, lane = t & 31;
    if (t == 0) { carry = 0; total = 0; }
    __syncthreads();

    for (int chunk = 0; chunk < NBLK_; chunk++) {
        int g = chunk * SCAN_B + t;
        int v = (g < N_NODES_) ? g_deg[g] : 0;
        int inc = v;
        #pragma unroll
        for (int d = 1; d < 32; d <<= 1) {
            int u = __shfl_up_sync(0xffffffffu, inc, d);
            if (lane >= d) inc += u;
        }
        if (lane == 31) wsum[wid] = inc;
        __syncthreads();
        if (t < 32) {
            int wv = wsum[t];
            int winc = wv;
            #pragma unroll
            for (int d = 1; d < 32; d <<= 1) {
                int u = __shfl_up_sync(0xffffffffu, winc, d);
                if (t >= d) winc += u;
            }
            wsum[t] = winc - wv;           // exclusive warp offset
            if (t == 31) total = winc;
        }
        __syncthreads();
        int ex = carry + wsum[wid] + inc - v;
        if (g < N_NODES_) { g_rowptr[g] = ex; g_cursor[g] = ex; }
        if (g == N_NODES_ - 1) g_rowptr[N_NODES_] = ex + v;
        __syncthreads();
        if (t == 0) carry += total;
        __syncthreads();
    }
}

__global__ void k_fill(const int* __restrict__ ei, const float* __restrict__ ea) {
    int e = blockIdx.x * blockDim.x + threadIdx.x;
    if (e >= N_EDGES_) return;
    int dst = ei[N_EDGES_ + e];
    int slot = atomicAdd(&g_cursor[dst], 1);
    g_csrc[slot] = ei[e];
    g_cea[slot]  = ea[e];
    g_ceid[slot] = e;
}

// ---------------------------------------------------------------------------
// Layer-0 (16 -> 128), fused gather + MLP. 256 thr / 8 warps / 128 nodes.
// Gather: half-warp (16 lanes) per node, lane = feature.
// ---------------------------------------------------------------------------
__global__ void __launch_bounds__(256)
node_mlp16_tc(const float* __restrict__ x,
              const float* __restrict__ We, const float* __restrict__ be,
              const float* __restrict__ b1, const float* __restrict__ b2,
              float* __restrict__ hout)
{
    extern __shared__ __align__(16) float Z[];

    int tid = threadIdx.x, w = tid >> 5, lane = tid & 31;
    int nb = blockIdx.x * 128;

    // fused aggregation gather: lanes 0-15 node even, 16-31 node odd
    {
        int f = lane & 15, half = lane >> 4;
        float wf = We[f], bf = be[f];
        for (int i = 0; i < 8; i++) {
            int row = w * 16 + 2 * i + half;
            int node = nb + row;
            float acc = 0.f;
            if (node < N_NODES_) {
                acc = x[node * NIN_ + f];
                int beg = g_rowptr[node], end = g_rowptr[node + 1];
                for (int p = beg; p < end; p++)
                    acc += fmaxf(x[g_csrc[p] * NIN_ + f] + g_cea[p] * wf + bf, 0.f);
            }
            Z[row * SSTR + f] = acc;
        }
    }
    __syncwarp();

    float c[16][4];
    const float* Zw = &Z[w * 16 * SSTR];
    int g = lane >> 2, t = lane & 3;

    mma_phase<2>(Zw, &g_WF[WF_W10], lane, c);
    __syncwarp();
    #pragma unroll
    for (int nt = 0; nt < 16; nt++) {
        int col = nt * 8 + 2 * t;
        float2 bb = *(const float2*)&b1[col];
        float2 e0 = make_float2(eluf(c[nt][0] + bb.x), eluf(c[nt][1] + bb.y));
        float2 e1 = make_float2(eluf(c[nt][2] + bb.x), eluf(c[nt][3] + bb.y));
        *(float2*)&Z[(w * 16 + g) * SSTR + col]     = e0;
        *(float2*)&Z[(w * 16 + g + 8) * SSTR + col] = e1;
    }
    __syncwarp();

    mma_phase<16>(Zw, &g_WF[WF_W20], lane, c);
    int n0 = nb + w * 16 + g;
    #pragma unroll
    for (int nt = 0; nt < 16; nt++) {
        int col = nt * 8 + 2 * t;
        float2 bb = *(const float2*)&b2[col];
        float2 e0 = make_float2(eluf(c[nt][0] + bb.x), eluf(c[nt][1] + bb.y));
        float2 e1 = make_float2(eluf(c[nt][2] + bb.x), eluf(c[nt][3] + bb.y));
        if (n0 < N_NODES_)     *(float2*)&hout[n0 * HID_ + col]       = e0;
        if (n0 + 8 < N_NODES_) *(float2*)&hout[(n0 + 8) * HID_ + col] = e1;
    }
}

// ---------------------------------------------------------------------------
// Fused GINE layer: CSR gather + 2 MMA phases. 256 thr / 8 warps / 128 nodes.
// ---------------------------------------------------------------------------
__global__ void __launch_bounds__(256)
gine_tc(const float* __restrict__ h,
        const float* __restrict__ We, const float* __restrict__ be,
        const uint4* __restrict__ WF1, const float* __restrict__ b1,
        const uint4* __restrict__ WF2, const float* __restrict__ b2,
        float* __restrict__ hout)
{
    extern __shared__ __align__(16) float Z[];

    int tid = threadIdx.x, w = tid >> 5, lane = tid & 31;
    int nb = blockIdx.x * 128;

    // gather prologue: each warp fills its 16 rows
    {
        float4 wv = ld4(&We[lane * 4]);
        float4 bg = ld4(&be[lane * 4]);
        for (int n = 0; n < 16; n++) {
            int node = nb + w * 16 + n;
            float4 acc = make_float4(0.f, 0.f, 0.f, 0.f);
            if (node < N_NODES_) {
                acc = ld4(&h[node * HID_ + lane * 4]);
                int beg = g_rowptr[node], end = g_rowptr[node + 1];
                for (int p = beg; p < end; p++) {
                    int s = g_csrc[p];
                    float we = g_cea[p];
                    float4 hv = ld4(&h[s * HID_ + lane * 4]);
                    acc.x += fmaxf(fmaf(we, wv.x, hv.x) + bg.x, 0.f);
                    acc.y += fmaxf(fmaf(we, wv.y, hv.y) + bg.y, 0.f);
                    acc.z += fmaxf(fmaf(we, wv.z, hv.z) + bg.z, 0.f);
                    acc.w += fmaxf(fmaf(we, wv.w, hv.w) + bg.w, 0.f);
                }
            }
            st4(&Z[(w * 16 + n) * SSTR + lane * 4], acc);
        }
    }
    __syncwarp();

    float c[16][4];
    const float* Zw = &Z[w * 16 * SSTR];
    int g = lane >> 2, t = lane & 3;

    mma_phase<16>(Zw, WF1, lane, c);
    __syncwarp();
    #pragma unroll
    for (int nt = 0; nt < 16; nt++) {
        int col = nt * 8 + 2 * t;
        float2 bb = *(const float2*)&b1[col];
        float2 e0 = make_float2(eluf(c[nt][0] + bb.x), eluf(c[nt][1] + bb.y));
        float2 e1 = make_float2(eluf(c[nt][2] + bb.x), eluf(c[nt][3] + bb.y));
        *(float2*)&Z[(w * 16 + g) * SSTR + col]     = e0;
        *(float2*)&Z[(w * 16 + g + 8) * SSTR + col] = e1;
    }
    __syncwarp();

    mma_phase<16>(Zw, WF2, lane, c);
    int n0 = nb + w * 16 + g;
    #pragma unroll
    for (int nt = 0; nt < 16; nt++) {
        int col = nt * 8 + 2 * t;
        float2 bb = *(const float2*)&b2[col];
        float2 e0 = make_float2(eluf(c[nt][0] + bb.x), eluf(c[nt][1] + bb.y));
        float2 e1 = make_float2(eluf(c[nt][2] + bb.x), eluf(c[nt][3] + bb.y));
        if (n0 < N_NODES_)     *(float2*)&hout[n0 * HID_ + col]       = e0;
        if (n0 + 8 < N_NODES_) *(float2*)&hout[(n0 + 8) * HID_ + col] = e1;
    }
}

// ---------------------------------------------------------------------------
// Edge-predictor node factors. 256 thr / 8 warps / 128 nodes.
// ---------------------------------------------------------------------------
__global__ void __launch_bounds__(256)
k_prednode_tc(const float* __restrict__ h, float* __restrict__ P)
{
    extern __shared__ __align__(16) float Z[];

    int tid = threadIdx.x, w = tid >> 5, lane = tid & 31;
    int nb = blockIdx.x * 128;

    for (int i = tid; i < 128 * 32; i += 256) {
        int row = i >> 5, c4 = i & 31;
        int node = nb + row;
        float4 v = make_float4(0.f, 0.f, 0.f, 0.f);
        if (node < N_NODES_) v = ld4(&h[node * HID_ + c4 * 4]);
        st4(&Z[row * SSTR + c4 * 4], v);
    }
    __syncthreads();

    float c[16][4];
    const float* Zw = &Z[w * 16 * SSTR];
    int g = lane >> 2, t = lane & 3;
    int n0 = nb + w * 16 + g;

    mma_phase<16>(Zw, &g_WF[WF_WPA], lane, c);
    #pragma unroll
    for (int nt = 0; nt < 16; nt++) {
        int col = nt * 8 + 2 * t;
        if (n0 < N_NODES_)     *(float2*)&P[n0 * 256 + col]       = make_float2(c[nt][0], c[nt][1]);
        if (n0 + 8 < N_NODES_) *(float2*)&P[(n0 + 8) * 256 + col] = make_float2(c[nt][2], c[nt][3]);
    }

    mma_phase<16>(Zw, &g_WF[WF_WPB], lane, c);
    #pragma unroll
    for (int nt = 0; nt < 16; nt++) {
        int col = nt * 8 + 2 * t;
        if (n0 < N_NODES_)     *(float2*)&P[n0 * 256 + 128 + col]       = make_float2(c[nt][0], c[nt][1]);
        if (n0 + 8 < N_NODES_) *(float2*)&P[(n0 + 8) * 256 + 128 + col] = make_float2(c[nt][2], c[nt][3]);
    }
}

// ---------------------------------------------------------------------------
// dst-major edge predictor epilogue: warp per node, B[dst] loaded once.
// out[eid] = elu(A[src]+B[dst]+bp1) . Wp2 + bp2
// ---------------------------------------------------------------------------
__global__ void k_prededge2(const float* __restrict__ P,
                            const float* __restrict__ bp1, const float* __restrict__ Wp2,
                            const float* __restrict__ bp2, float* __restrict__ out)
{
    int node = (blockIdx.x * blockDim.x + threadIdx.x) >> 5;
    int lane = threadIdx.x & 31;
    if (node >= N_NODES_) return;

    float4 b  = ld4(&P[node * 256 + 128 + lane * 4]);
    float4 bv = ld4(&bp1[lane * 4]);
    float4 w2 = ld4(&Wp2[lane * 4]);
    float cc = bp2[0];
    b.x += bv.x; b.y += bv.y; b.z += bv.z; b.w += bv.w;

    int beg = g_rowptr[node], end = g_rowptr[node + 1];
    for (int p = beg; p < end; p++) {
        int src = g_csrc[p];
        float4 a = ld4(&P[src * 256 + lane * 4]);
        float tx = eluf(a.x + b.x), ty = eluf(a.y + b.y);
        float tz = eluf(a.z + b.z), tw = eluf(a.w + b.w);
        float d = tx * w2.x + ty * w2.y + tz * w2.z + tw * w2.w;
        #pragma unroll
        for (int off = 16; off; off >>= 1)
            d += __shfl_xor_sync(0xffffffffu, d, off);
        if (lane == 0) out[g_ceid[p]] = d + cc;
    }
}

// ---------------------------------------------------------------------------
extern "C" void kernel_launch(void* const* d_in, const int* in_sizes, int n_in,
                              void* d_out, int out_size)
{
    const float* x    = (const float*)d_in[0];
    const int*   ei   = (const int*)  d_in[1];
    const float* ea   = (const float*)d_in[2];
    const float* We0  = (const float*)d_in[3];
    const float* be0  = (const float*)d_in[4];
    const float* W10  = (const float*)d_in[5];
    const float* b10  = (const float*)d_in[6];
    const float* W20  = (const float*)d_in[7];
    const float* b20  = (const float*)d_in[8];
    const float* We_s = (const float*)d_in[9];
    const float* be_s = (const float*)d_in[10];
    const float* W1_s = (const float*)d_in[11];
    const float* b1_s = (const float*)d_in[12];
    const float* W2_s = (const float*)d_in[13];
    const float* b2_s = (const float*)d_in[14];
    const float* Wp1  = (const float*)d_in[15];
    const float* bp1  = (const float*)d_in[16];
    const float* Wp2  = (const float*)d_in[17];
    const float* bp2  = (const float*)d_in[18];
    float* out = (float*)d_out;

    float *hA, *hB, *P;
    uint4* WF;
    int *deg;
    cudaGetSymbolAddress((void**)&hA, g_h);
    cudaGetSymbolAddress((void**)&hB, g_hn);
    cudaGetSymbolAddress((void**)&P,  g_P);
    cudaGetSymbolAddress((void**)&WF, g_WF);
    cudaGetSymbolAddress((void**)&deg, g_deg);

    static int smem_set = 0;
    if (!smem_set) {
        cudaFuncSetAttribute(node_mlp16_tc, cudaFuncAttributeMaxDynamicSharedMemorySize, SMEM_TC);
        cudaFuncSetAttribute(gine_tc,       cudaFuncAttributeMaxDynamicSharedMemorySize, SMEM_TC);
        cudaFuncSetAttribute(k_prednode_tc, cudaFuncAttributeMaxDynamicSharedMemorySize, SMEM_TC);
        smem_set = 1;
    }

    // ---- prep: weight fragments + CSR build ----
    cudaMemsetAsync(deg, 0, N_NODES_ * sizeof(int));
    k_wfrag<<<(WF_TOTAL + 255) / 256, 256>>>(W10, W20, W1_s, W2_s, Wp1);
    k_hist <<<(N_EDGES_ + 255) / 256, 256>>>(ei);
    k_scan1<<<1, SCAN_B>>>();
    k_fill <<<(N_EDGES_ + 255) / 256, 256>>>(ei, ea);

    // ---- Layer 0 (16 -> 128), fused gather + MLP ----
    node_mlp16_tc<<<NODE_BLKS, 256, SMEM_TC>>>(x, We0, be0, b10, b20, hA);

    // ---- Layers 1..4 ----
    for (int l = 0; l < 4; l++) {
        gine_tc<<<NODE_BLKS, 256, SMEM_TC>>>(hA,
                                             We_s + l * HID_, be_s + l * HID_,
                                             WF + WF_W1 + l * 8192, b1_s + l * HID_,
                                             WF + WF_W2 + l * 8192, b2_s + l * HID_, hB);
        float* t = hA; hA = hB; hB = t;
    }

    // ---- Edge predictor ----
    k_prednode_tc<<<NODE_BLKS, 256, SMEM_TC>>>(hA, P);
    k_prededge2<<<(N_NODES_ * 32 + 255) / 256, 256>>>(P, bp1, Wp2, bp2, out);
}

// round 8
// speedup vs baseline: 1.2120x; 1.2120x over previous
#include <cuda_runtime.h>
#include <math.h>

#define N_NODES_ 100000
#define N_EDGES_ 500000
#define HID_ 128
#define NIN_ 16
#define SCAN_B 1024
#define NBLK_ ((N_NODES_ + SCAN_B - 1) / SCAN_B)   // 98
#define NODE_BLKS ((N_NODES_ + 63) / 64)           // 1563
#define SSTR 132                                   // smem row stride (floats), conflict-free

typedef unsigned int uint32;

// ---- static scratch (no allocations allowed) ----
__device__ float g_h  [N_NODES_ * HID_];
__device__ float g_hn [N_NODES_ * HID_];
__device__ float g_P  [N_NODES_ * 2 * HID_];
__device__ int   g_deg   [N_NODES_];
__device__ int   g_rowptr[N_NODES_ + 1];
__device__ int   g_cursor[N_NODES_];
__device__ int   g_csrc  [N_EDGES_];
__device__ int   g_ceid  [N_EDGES_];
__device__ float g_cea   [N_EDGES_];

// ---- fragment-ordered TF32 hi/lo weights: [kstep][ntile][lane] = {bhi0,bhi1,blo0,blo1}
#define WF_W10 0                 // K=16 : 2*16*32   = 1024
#define WF_W20 1024              // K=128: 16*16*32  = 8192
#define WF_W1  9216              // 4 x 8192
#define WF_W2  41984             // 4 x 8192
#define WF_WPA 74752             // Wp1 rows 0..127
#define WF_WPB 82944             // Wp1 rows 128..255
#define WF_TOTAL 91136
__device__ uint4 g_WF[WF_TOTAL];

__device__ __forceinline__ float4 ld4(const float* p) { return *reinterpret_cast<const float4*>(p); }
__device__ __forceinline__ void st4(float* p, float4 v) { *reinterpret_cast<float4*>(p) = v; }
__device__ __forceinline__ float eluf(float x) { return x > 0.f ? x : expm1f(x); }

// ---- tf32 helpers ----
__device__ __forceinline__ uint32 tf32_hi(float f) {
    uint32 r; asm("cvt.rna.tf32.f32 %0, %1;" : "=r"(r) : "f"(f)); return r;
}
__device__ __forceinline__ uint32 tf32_lo(float f, uint32 hi) {
    return tf32_hi(f - __uint_as_float(hi));
}

// D += A(tf32) * B(tf32), m16n8k8
__device__ __forceinline__ void mma8(float c[4], uint32 a0, uint32 a1, uint32 a2, uint32 a3,
                                     uint32 b0, uint32 b1)
{
    asm volatile(
        "mma.sync.aligned.m16n8k8.row.col.f32.tf32.tf32.f32 "
        "{%0,%1,%2,%3}, {%4,%5,%6,%7}, {%8,%9}, {%0,%1,%2,%3};"
        : "+f"(c[0]), "+f"(c[1]), "+f"(c[2]), "+f"(c[3])
        : "r"(a0), "r"(a1), "r"(a2), "r"(a3), "r"(b0), "r"(b1));
}

// ---------------------------------------------------------------------------
// One MMA phase: warp computes C[16 rows x 128 cols] = Zw @ W (3xTF32 split).
// ---------------------------------------------------------------------------
template <int KSTEPS>
__device__ __forceinline__ void mma_phase(const float* Zw, const uint4* __restrict__ WF,
                                          int lane, float c[16][4])
{
    int g = lane >> 2, t = lane & 3;
    #pragma unroll
    for (int nt = 0; nt < 16; nt++) { c[nt][0] = 0.f; c[nt][1] = 0.f; c[nt][2] = 0.f; c[nt][3] = 0.f; }

    #pragma unroll 1
    for (int ks = 0; ks < KSTEPS; ks++) {
        float z0 = Zw[g * SSTR + ks * 8 + t];
        float z1 = Zw[(g + 8) * SSTR + ks * 8 + t];
        float z2 = Zw[g * SSTR + ks * 8 + t + 4];
        float z3 = Zw[(g + 8) * SSTR + ks * 8 + t + 4];
        uint32 ah0 = tf32_hi(z0), ah1 = tf32_hi(z1), ah2 = tf32_hi(z2), ah3 = tf32_hi(z3);
        uint32 al0 = tf32_lo(z0, ah0), al1 = tf32_lo(z1, ah1);
        uint32 al2 = tf32_lo(z2, ah2), al3 = tf32_lo(z3, ah3);
        const uint4* wrow = &WF[ks * 16 * 32 + lane];
        #pragma unroll
        for (int nt = 0; nt < 16; nt++) {
            uint4 wf = wrow[nt * 32];
            mma8(c[nt], ah0, ah1, ah2, ah3, wf.x, wf.y);   // Ahi*Bhi
            mma8(c[nt], al0, al1, al2, al3, wf.x, wf.y);   // Alo*Bhi
            mma8(c[nt], ah0, ah1, ah2, ah3, wf.z, wf.w);   // Ahi*Blo
        }
    }
}

// ---------------------------------------------------------------------------
// Weight fragment prep (once per launch)
// ---------------------------------------------------------------------------
__global__ void k_wfrag(const float* __restrict__ W10, const float* __restrict__ W20,
                        const float* __restrict__ W1s, const float* __restrict__ W2s,
                        const float* __restrict__ Wp1)
{
    int i = blockIdx.x * 256 + threadIdx.x;
    if (i >= WF_TOTAL) return;
    const float* W; int idx;
    if (i < 1024)        { W = W10; idx = i; }
    else if (i < 9216)   { W = W20; idx = i - 1024; }
    else if (i < 41984)  { int j = i - 9216;  W = W1s + (j >> 13) * 16384; idx = j & 8191; }
    else if (i < 74752)  { int j = i - 41984; W = W2s + (j >> 13) * 16384; idx = j & 8191; }
    else if (i < 82944)  { W = Wp1;           idx = i - 74752; }
    else                 { W = Wp1 + 16384;   idx = i - 82944; }
    int lane = idx & 31, nt = (idx >> 5) & 15, ks = idx >> 9;
    int k0 = ks * 8 + (lane & 3);
    int n  = nt * 8 + (lane >> 2);
    float w0 = W[k0 * 128 + n];
    float w1 = W[(k0 + 4) * 128 + n];
    uint32 h0 = tf32_hi(w0), h1 = tf32_hi(w1);
    g_WF[i] = make_uint4(h0, h1, tf32_lo(w0, h0), tf32_lo(w1, h1));
}

// ---------------------------------------------------------------------------
// CSR build
// ---------------------------------------------------------------------------
__global__ void k_hist(const int* __restrict__ ei) {
    int e = blockIdx.x * blockDim.x + threadIdx.x;
    if (e < N_EDGES_) atomicAdd(&g_deg[ei[N_EDGES_ + e]], 1);
}

// Single-block exclusive scan over g_deg -> g_rowptr/g_cursor
__global__ void k_scan1() {
    __shared__ int wsum[32];
    __shared__ int carry, total;
    int t = threadIdx.x;
    int wid = t >> 5, lane = t & 31;
    if (t == 0) { carry = 0; total = 0; }
    __syncthreads();

    for (int chunk = 0; chunk < NBLK_; chunk++) {
        int g = chunk * SCAN_B + t;
        int v = (g < N_NODES_) ? g_deg[g] : 0;
        int inc = v;
        #pragma unroll
        for (int d = 1; d < 32; d <<= 1) {
            int u = __shfl_up_sync(0xffffffffu, inc, d);
            if (lane >= d) inc += u;
        }
        if (lane == 31) wsum[wid] = inc;
        __syncthreads();
        if (t < 32) {
            int wv = wsum[t];
            int winc = wv;
            #pragma unroll
            for (int d = 1; d < 32; d <<= 1) {
                int u = __shfl_up_sync(0xffffffffu, winc, d);
                if (t >= d) winc += u;
            }
            wsum[t] = winc - wv;           // exclusive warp offset
            if (t == 31) total = winc;
        }
        __syncthreads();
        int ex = carry + wsum[wid] + inc - v;
        if (g < N_NODES_) { g_rowptr[g] = ex; g_cursor[g] = ex; }
        if (g == N_NODES_ - 1) g_rowptr[N_NODES_] = ex + v;
        __syncthreads();
        if (t == 0) carry += total;
        __syncthreads();
    }
}

__global__ void k_fill(const int* __restrict__ ei, const float* __restrict__ ea) {
    int e = blockIdx.x * blockDim.x + threadIdx.x;
    if (e >= N_EDGES_) return;
    int dst = ei[N_EDGES_ + e];
    int slot = atomicAdd(&g_cursor[dst], 1);
    g_csrc[slot] = ei[e];
    g_cea[slot]  = ea[e];
    g_ceid[slot] = e;
}

// ---------------------------------------------------------------------------
// Layer-0 (16 -> 128), fused gather + MLP. 128 thr / 4 warps / 64 nodes.
// Gather: half-warp (16 lanes) per node, lane = feature.
// ---------------------------------------------------------------------------
__global__ void __launch_bounds__(128)
node_mlp16_tc(const float* __restrict__ x,
              const float* __restrict__ We, const float* __restrict__ be,
              const float* __restrict__ b1, const float* __restrict__ b2,
              float* __restrict__ hout)
{
    __shared__ __align__(16) float Z[64 * SSTR];

    int tid = threadIdx.x, w = tid >> 5, lane = tid & 31;
    int nb = blockIdx.x * 64;

    // fused aggregation gather: lanes 0-15 node even, 16-31 node odd
    {
        int f = lane & 15, half = lane >> 4;
        float wf = We[f], bf = be[f];
        for (int i = 0; i < 8; i++) {
            int row = w * 16 + 2 * i + half;
            int node = nb + row;
            float acc = 0.f;
            if (node < N_NODES_) {
                acc = x[node * NIN_ + f];
                int beg = g_rowptr[node], end = g_rowptr[node + 1];
                for (int p = beg; p < end; p++)
                    acc += fmaxf(x[g_csrc[p] * NIN_ + f] + g_cea[p] * wf + bf, 0.f);
            }
            Z[row * SSTR + f] = acc;
        }
    }
    __syncwarp();

    float c[16][4];
    const float* Zw = &Z[w * 16 * SSTR];
    int g = lane >> 2, t = lane & 3;

    mma_phase<2>(Zw, &g_WF[WF_W10], lane, c);
    __syncwarp();
    #pragma unroll
    for (int nt = 0; nt < 16; nt++) {
        int col = nt * 8 + 2 * t;
        float2 bb = *(const float2*)&b1[col];
        float2 e0 = make_float2(eluf(c[nt][0] + bb.x), eluf(c[nt][1] + bb.y));
        float2 e1 = make_float2(eluf(c[nt][2] + bb.x), eluf(c[nt][3] + bb.y));
        *(float2*)&Z[(w * 16 + g) * SSTR + col]     = e0;
        *(float2*)&Z[(w * 16 + g + 8) * SSTR + col] = e1;
    }
    __syncwarp();

    mma_phase<16>(Zw, &g_WF[WF_W20], lane, c);
    int n0 = nb + w * 16 + g;
    #pragma unroll
    for (int nt = 0; nt < 16; nt++) {
        int col = nt * 8 + 2 * t;
        float2 bb = *(const float2*)&b2[col];
        float2 e0 = make_float2(eluf(c[nt][0] + bb.x), eluf(c[nt][1] + bb.y));
        float2 e1 = make_float2(eluf(c[nt][2] + bb.x), eluf(c[nt][3] + bb.y));
        if (n0 < N_NODES_)     *(float2*)&hout[n0 * HID_ + col]       = e0;
        if (n0 + 8 < N_NODES_) *(float2*)&hout[(n0 + 8) * HID_ + col] = e1;
    }
}

// ---------------------------------------------------------------------------
// Fused GINE layer: CSR gather + 2 MMA phases. 128 thr / 4 warps / 64 nodes.
// Gather loop software-pipelined (next index prefetched under current load).
// ---------------------------------------------------------------------------
__global__ void __launch_bounds__(128)
gine_tc(const float* __restrict__ h,
        const float* __restrict__ We, const float* __restrict__ be,
        const uint4* __restrict__ WF1, const float* __restrict__ b1,
        const uint4* __restrict__ WF2, const float* __restrict__ b2,
        float* __restrict__ hout)
{
    __shared__ __align__(16) float Z[64 * SSTR];

    int tid = threadIdx.x, w = tid >> 5, lane = tid & 31;
    int nb = blockIdx.x * 64;

    // gather prologue: each warp fills its 16 rows
    {
        float4 wv = ld4(&We[lane * 4]);
        float4 bg = ld4(&be[lane * 4]);
        for (int n = 0; n < 16; n++) {
            int node = nb + w * 16 + n;
            float4 acc = make_float4(0.f, 0.f, 0.f, 0.f);
            if (node < N_NODES_) {
                acc = ld4(&h[node * HID_ + lane * 4]);
                int beg = g_rowptr[node], end = g_rowptr[node + 1];
                int s = 0; float we = 0.f;
                if (beg < end) { s = g_csrc[beg]; we = g_cea[beg]; }
                for (int p = beg; p < end; p++) {
                    float4 hv = ld4(&h[s * HID_ + lane * 4]);
                    float wec = we;
                    if (p + 1 < end) { s = g_csrc[p + 1]; we = g_cea[p + 1]; }
                    acc.x += fmaxf(fmaf(wec, wv.x, hv.x) + bg.x, 0.f);
                    acc.y += fmaxf(fmaf(wec, wv.y, hv.y) + bg.y, 0.f);
                    acc.z += fmaxf(fmaf(wec, wv.z, hv.z) + bg.z, 0.f);
                    acc.w += fmaxf(fmaf(wec, wv.w, hv.w) + bg.w, 0.f);
                }
            }
            st4(&Z[(w * 16 + n) * SSTR + lane * 4], acc);
        }
    }
    __syncwarp();

    float c[16][4];
    const float* Zw = &Z[w * 16 * SSTR];
    int g = lane >> 2, t = lane & 3;

    mma_phase<16>(Zw, WF1, lane, c);
    __syncwarp();
    #pragma unroll
    for (int nt = 0; nt < 16; nt++) {
        int col = nt * 8 + 2 * t;
        float2 bb = *(const float2*)&b1[col];
        float2 e0 = make_float2(eluf(c[nt][0] + bb.x), eluf(c[nt][1] + bb.y));
        float2 e1 = make_float2(eluf(c[nt][2] + bb.x), eluf(c[nt][3] + bb.y));
        *(float2*)&Z[(w * 16 + g) * SSTR + col]     = e0;
        *(float2*)&Z[(w * 16 + g + 8) * SSTR + col] = e1;
    }
    __syncwarp();

    mma_phase<16>(Zw, WF2, lane, c);
    int n0 = nb + w * 16 + g;
    #pragma unroll
    for (int nt = 0; nt < 16; nt++) {
        int col = nt * 8 + 2 * t;
        float2 bb = *(const float2*)&b2[col];
        float2 e0 = make_float2(eluf(c[nt][0] + bb.x), eluf(c[nt][1] + bb.y));
        float2 e1 = make_float2(eluf(c[nt][2] + bb.x), eluf(c[nt][3] + bb.y));
        if (n0 < N_NODES_)     *(float2*)&hout[n0 * HID_ + col]       = e0;
        if (n0 + 8 < N_NODES_) *(float2*)&hout[(n0 + 8) * HID_ + col] = e1;
    }
}

// ---------------------------------------------------------------------------
// Edge-predictor node factors. 128 thr / 4 warps / 64 nodes.
// ---------------------------------------------------------------------------
__global__ void __launch_bounds__(128)
k_prednode_tc(const float* __restrict__ h, float* __restrict__ P)
{
    __shared__ __align__(16) float Z[64 * SSTR];

    int tid = threadIdx.x, w = tid >> 5, lane = tid & 31;
    int nb = blockIdx.x * 64;

    for (int i = tid; i < 64 * 32; i += 128) {
        int row = i >> 5, c4 = i & 31;
        int node = nb + row;
        float4 v = make_float4(0.f, 0.f, 0.f, 0.f);
        if (node < N_NODES_) v = ld4(&h[node * HID_ + c4 * 4]);
        st4(&Z[row * SSTR + c4 * 4], v);
    }
    __syncthreads();

    float c[16][4];
    const float* Zw = &Z[w * 16 * SSTR];
    int g = lane >> 2, t = lane & 3;
    int n0 = nb + w * 16 + g;

    mma_phase<16>(Zw, &g_WF[WF_WPA], lane, c);
    #pragma unroll
    for (int nt = 0; nt < 16; nt++) {
        int col = nt * 8 + 2 * t;
        if (n0 < N_NODES_)     *(float2*)&P[n0 * 256 + col]       = make_float2(c[nt][0], c[nt][1]);
        if (n0 + 8 < N_NODES_) *(float2*)&P[(n0 + 8) * 256 + col] = make_float2(c[nt][2], c[nt][3]);
    }

    mma_phase<16>(Zw, &g_WF[WF_WPB], lane, c);
    #pragma unroll
    for (int nt = 0; nt < 16; nt++) {
        int col = nt * 8 + 2 * t;
        if (n0 < N_NODES_)     *(float2*)&P[n0 * 256 + 128 + col]       = make_float2(c[nt][0], c[nt][1]);
        if (n0 + 8 < N_NODES_) *(float2*)&P[(n0 + 8) * 256 + 128 + col] = make_float2(c[nt][2], c[nt][3]);
    }
}

// ---------------------------------------------------------------------------
// dst-major edge predictor epilogue: warp per node, B[dst] loaded once.
// out[eid] = elu(A[src]+B[dst]+bp1) . Wp2 + bp2
// ---------------------------------------------------------------------------
__global__ void k_prededge2(const float* __restrict__ P,
                            const float* __restrict__ bp1, const float* __restrict__ Wp2,
                            const float* __restrict__ bp2, float* __restrict__ out)
{
    int node = (blockIdx.x * blockDim.x + threadIdx.x) >> 5;
    int lane = threadIdx.x & 31;
    if (node >= N_NODES_) return;

    float4 b  = ld4(&P[node * 256 + 128 + lane * 4]);
    float4 bv = ld4(&bp1[lane * 4]);
    float4 w2 = ld4(&Wp2[lane * 4]);
    float cc = bp2[0];
    b.x += bv.x; b.y += bv.y; b.z += bv.z; b.w += bv.w;

    int beg = g_rowptr[node], end = g_rowptr[node + 1];
    for (int p = beg; p < end; p++) {
        int src = g_csrc[p];
        float4 a = ld4(&P[src * 256 + lane * 4]);
        float tx = eluf(a.x + b.x), ty = eluf(a.y + b.y);
        float tz = eluf(a.z + b.z), tw = eluf(a.w + b.w);
        float d = tx * w2.x + ty * w2.y + tz * w2.z + tw * w2.w;
        #pragma unroll
        for (int off = 16; off; off >>= 1)
            d += __shfl_xor_sync(0xffffffffu, d, off);
        if (lane == 0) out[g_ceid[p]] = d + cc;
    }
}

// ---------------------------------------------------------------------------
extern "C" void kernel_launch(void* const* d_in, const int* in_sizes, int n_in,
                              void* d_out, int out_size)
{
    const float* x    = (const float*)d_in[0];
    const int*   ei   = (const int*)  d_in[1];
    const float* ea   = (const float*)d_in[2];
    const float* We0  = (const float*)d_in[3];
    const float* be0  = (const float*)d_in[4];
    const float* W10  = (const float*)d_in[5];
    const float* b10  = (const float*)d_in[6];
    const float* W20  = (const float*)d_in[7];
    const float* b20  = (const float*)d_in[8];
    const float* We_s = (const float*)d_in[9];
    const float* be_s = (const float*)d_in[10];
    const float* W1_s = (const float*)d_in[11];
    const float* b1_s = (const float*)d_in[12];
    const float* W2_s = (const float*)d_in[13];
    const float* b2_s = (const float*)d_in[14];
    const float* Wp1  = (const float*)d_in[15];
    const float* bp1  = (const float*)d_in[16];
    const float* Wp2  = (const float*)d_in[17];
    const float* bp2  = (const float*)d_in[18];
    float* out = (float*)d_out;

    float *hA, *hB, *P;
    uint4* WF;
    int *deg;
    cudaGetSymbolAddress((void**)&hA, g_h);
    cudaGetSymbolAddress((void**)&hB, g_hn);
    cudaGetSymbolAddress((void**)&P,  g_P);
    cudaGetSymbolAddress((void**)&WF, g_WF);
    cudaGetSymbolAddress((void**)&deg, g_deg);

    // ---- prep: weight fragments + CSR build (5 launches before first layer) ----
    cudaMemsetAsync(deg, 0, N_NODES_ * sizeof(int));
    k_wfrag<<<(WF_TOTAL + 255) / 256, 256>>>(W10, W20, W1_s, W2_s, Wp1);
    k_hist <<<(N_EDGES_ + 255) / 256, 256>>>(ei);
    k_scan1<<<1, SCAN_B>>>();
    k_fill <<<(N_EDGES_ + 255) / 256, 256>>>(ei, ea);

    // ---- Layer 0 (16 -> 128), fused gather + MLP ----
    node_mlp16_tc<<<NODE_BLKS, 128>>>(x, We0, be0, b10, b20, hA);

    // ---- Layers 1..4 ----
    for (int l = 0; l < 4; l++) {
        gine_tc<<<NODE_BLKS, 128>>>(hA,
                                    We_s + l * HID_, be_s + l * HID_,
                                    WF + WF_W1 + l * 8192, b1_s + l * HID_,
                                    WF + WF_W2 + l * 8192, b2_s + l * HID_, hB);
        float* t = hA; hA = hB; hB = t;
    }

    // ---- Edge predictor ----
    k_prednode_tc<<<NODE_BLKS, 128>>>(hA, P);
    k_prededge2<<<(N_NODES_ * 32 + 255) / 256, 256>>>(P, bp1, Wp2, bp2, out);
}

// round 9
// speedup vs baseline: 1.2509x; 1.0322x over previous
#include <cuda_runtime.h>
#include <math.h>

#define N_NODES_ 100000
#define N_EDGES_ 500000
#define HID_ 128
#define NIN_ 16
#define SCAN_B 1024
#define NBLK_ ((N_NODES_ + SCAN_B - 1) / SCAN_B)   // 98
#define NODE_BLKS ((N_NODES_ + 63) / 64)           // 1563
#define SSTR 132                                   // smem row stride (floats), conflict-free

typedef unsigned int uint32;

// ---- static scratch (no allocations allowed) ----
__device__ float g_h  [N_NODES_ * HID_];
__device__ float g_hn [N_NODES_ * HID_];
__device__ float g_P  [N_NODES_ * 2 * HID_];   // predictor factors; reused as aggr scratch
__device__ int   g_deg   [N_NODES_];
__device__ int   g_incl  [N_NODES_];
__device__ int   g_rowptr[N_NODES_ + 1];
__device__ int   g_cursor[N_NODES_];
__device__ int   g_bsum  [NBLK_];
__device__ int   g_boff  [NBLK_];
__device__ int   g_csrc  [N_EDGES_];
__device__ float g_cea   [N_EDGES_];

// ---- fragment-ordered TF32 hi/lo weights: [kstep][ntile][lane] = {bhi0,bhi1,blo0,blo1}
#define WF_W10 0                 // K=16 : 2*16*32   = 1024
#define WF_W20 1024              // K=128: 16*16*32  = 8192
#define WF_W1  9216              // 4 x 8192
#define WF_W2  41984             // 4 x 8192
#define WF_WPA 74752             // Wp1 rows 0..127
#define WF_WPB 82944             // Wp1 rows 128..255
#define WF_TOTAL 91136
__device__ uint4 g_WF[WF_TOTAL];

__device__ __forceinline__ float4 ld4(const float* p) { return *reinterpret_cast<const float4*>(p); }
__device__ __forceinline__ void st4(float* p, float4 v) { *reinterpret_cast<float4*>(p) = v; }
__device__ __forceinline__ float eluf(float x) { return x > 0.f ? x : expm1f(x); }

// ---- tf32 helpers ----
__device__ __forceinline__ uint32 tf32_hi(float f) {
    uint32 r; asm("cvt.rna.tf32.f32 %0, %1;" : "=r"(r) : "f"(f)); return r;
}
__device__ __forceinline__ uint32 tf32_lo(float f, uint32 hi) {
    return tf32_hi(f - __uint_as_float(hi));
}

// D += A(tf32) * B(tf32), m16n8k8
__device__ __forceinline__ void mma8(float c[4], uint32 a0, uint32 a1, uint32 a2, uint32 a3,
                                     uint32 b0, uint32 b1)
{
    asm volatile(
        "mma.sync.aligned.m16n8k8.row.col.f32.tf32.tf32.f32 "
        "{%0,%1,%2,%3}, {%4,%5,%6,%7}, {%8,%9}, {%0,%1,%2,%3};"
        : "+f"(c[0]), "+f"(c[1]), "+f"(c[2]), "+f"(c[3])
        : "r"(a0), "r"(a1), "r"(a2), "r"(a3), "r"(b0), "r"(b1));
}

// ---------------------------------------------------------------------------
// One MMA phase: warp computes C[16 rows x 128 cols] = Zw @ W (3xTF32 split).
// ---------------------------------------------------------------------------
template <int KSTEPS>
__device__ __forceinline__ void mma_phase(const float* Zw, const uint4* __restrict__ WF,
                                          int lane, float c[16][4])
{
    int g = lane >> 2, t = lane & 3;
    #pragma unroll
    for (int nt = 0; nt < 16; nt++) { c[nt][0] = 0.f; c[nt][1] = 0.f; c[nt][2] = 0.f; c[nt][3] = 0.f; }

    #pragma unroll 1
    for (int ks = 0; ks < KSTEPS; ks++) {
        float z0 = Zw[g * SSTR + ks * 8 + t];
        float z1 = Zw[(g + 8) * SSTR + ks * 8 + t];
        float z2 = Zw[g * SSTR + ks * 8 + t + 4];
        float z3 = Zw[(g + 8) * SSTR + ks * 8 + t + 4];
        uint32 ah0 = tf32_hi(z0), ah1 = tf32_hi(z1), ah2 = tf32_hi(z2), ah3 = tf32_hi(z3);
        uint32 al0 = tf32_lo(z0, ah0), al1 = tf32_lo(z1, ah1);
        uint32 al2 = tf32_lo(z2, ah2), al3 = tf32_lo(z3, ah3);
        const uint4* wrow = &WF[ks * 16 * 32 + lane];
        #pragma unroll
        for (int nt = 0; nt < 16; nt++) {
            uint4 wf = wrow[nt * 32];
            mma8(c[nt], ah0, ah1, ah2, ah3, wf.x, wf.y);   // Ahi*Bhi
            mma8(c[nt], al0, al1, al2, al3, wf.x, wf.y);   // Alo*Bhi
            mma8(c[nt], ah0, ah1, ah2, ah3, wf.z, wf.w);   // Ahi*Blo
        }
    }
}

// ---------------------------------------------------------------------------
// Weight fragment prep (once per launch)
// ---------------------------------------------------------------------------
__global__ void k_wfrag(const float* __restrict__ W10, const float* __restrict__ W20,
                        const float* __restrict__ W1s, const float* __restrict__ W2s,
                        const float* __restrict__ Wp1)
{
    int i = blockIdx.x * 256 + threadIdx.x;
    if (i >= WF_TOTAL) return;
    const float* W; int idx;
    if (i < 1024)        { W = W10; idx = i; }
    else if (i < 9216)   { W = W20; idx = i - 1024; }
    else if (i < 41984)  { int j = i - 9216;  W = W1s + (j >> 13) * 16384; idx = j & 8191; }
    else if (i < 74752)  { int j = i - 41984; W = W2s + (j >> 13) * 16384; idx = j & 8191; }
    else if (i < 82944)  { W = Wp1;           idx = i - 74752; }
    else                 { W = Wp1 + 16384;   idx = i - 82944; }
    int lane = idx & 31, nt = (idx >> 5) & 15, ks = idx >> 9;
    int k0 = ks * 8 + (lane & 3);
    int n  = nt * 8 + (lane >> 2);
    float w0 = W[k0 * 128 + n];
    float w1 = W[(k0 + 4) * 128 + n];
    uint32 h0 = tf32_hi(w0), h1 = tf32_hi(w1);
    g_WF[i] = make_uint4(h0, h1, tf32_lo(w0, h0), tf32_lo(w1, h1));
}

// ---------------------------------------------------------------------------
// CSR build
// ---------------------------------------------------------------------------
__global__ void k_hist(const int* __restrict__ ei) {
    int e = blockIdx.x * blockDim.x + threadIdx.x;
    if (e < N_EDGES_) atomicAdd(&g_deg[ei[N_EDGES_ + e]], 1);
}

__global__ void k_scanA() {
    __shared__ int s[SCAN_B];
    int t = threadIdx.x;
    int g = blockIdx.x * SCAN_B + t;
    int v = (g < N_NODES_) ? g_deg[g] : 0;
    s[t] = v; __syncthreads();
    for (int d = 1; d < SCAN_B; d <<= 1) {
        int u = (t >= d) ? s[t - d] : 0;
        __syncthreads(); s[t] += u; __syncthreads();
    }
    if (g < N_NODES_) g_incl[g] = s[t];
    if (t == SCAN_B - 1) g_bsum[blockIdx.x] = s[t];
}

__global__ void k_scanB() {
    __shared__ int s[128];
    int t = threadIdx.x;
    int v = (t < NBLK_) ? g_bsum[t] : 0;
    s[t] = v; __syncthreads();
    for (int d = 1; d < 128; d <<= 1) {
        int u = (t >= d) ? s[t - d] : 0;
        __syncthreads(); s[t] += u; __syncthreads();
    }
    if (t < NBLK_) g_boff[t] = s[t] - v;
}

__global__ void k_scanC() {
    int g = blockIdx.x * SCAN_B + threadIdx.x;
    if (g >= N_NODES_) return;
    int ex = g_incl[g] - g_deg[g] + g_boff[blockIdx.x];
    g_rowptr[g] = ex;
    g_cursor[g] = ex;
    if (g == N_NODES_ - 1) g_rowptr[N_NODES_] = g_incl[g] + g_boff[blockIdx.x];
}

__global__ void k_fill(const int* __restrict__ ei, const float* __restrict__ ea) {
    int e = blockIdx.x * blockDim.x + threadIdx.x;
    if (e >= N_EDGES_) return;
    int dst = ei[N_EDGES_ + e];
    int slot = atomicAdd(&g_cursor[dst], 1);
    g_csrc[slot] = ei[e];
    g_cea[slot]  = ea[e];
}

// ---------------------------------------------------------------------------
// Layer-0 aggregation (16 features) via CSR gather
// ---------------------------------------------------------------------------
__global__ void k_aggr0(const float* __restrict__ x, const float* __restrict__ We,
                        const float* __restrict__ be, float* __restrict__ aggr)
{
    int t = blockIdx.x * blockDim.x + threadIdx.x;
    int node = t >> 4;
    int f = t & 15;
    if (node >= N_NODES_) return;
    int beg = g_rowptr[node], end = g_rowptr[node + 1];
    float w = We[f], b = be[f], acc = 0.f;
    for (int p = beg; p < end; p++) {
        float m = x[g_csrc[p] * NIN_ + f] + g_cea[p] * w + b;
        acc += fmaxf(m, 0.f);
    }
    aggr[node * NIN_ + f] = acc;
}

// ---------------------------------------------------------------------------
// HID aggregation via CSR gather — warp per node, lane-parallel float4.
// aggr[node] = h[node] + sum_e relu(h[src] + ea*We + be)
// ---------------------------------------------------------------------------
__global__ void k_aggr_hid(const float* __restrict__ h,
                           const float* __restrict__ We, const float* __restrict__ be,
                           float* __restrict__ aggr)
{
    int node = (blockIdx.x * blockDim.x + threadIdx.x) >> 5;
    int lane = threadIdx.x & 31;
    if (node >= N_NODES_) return;

    float4 wv = ld4(&We[lane * 4]);
    float4 bg = ld4(&be[lane * 4]);
    float4 acc = ld4(&h[node * HID_ + lane * 4]);

    int beg = g_rowptr[node], end = g_rowptr[node + 1];
    for (int p = beg; p < end; p++) {
        int s = g_csrc[p];
        float we = g_cea[p];
        float4 hv = ld4(&h[s * HID_ + lane * 4]);
        acc.x += fmaxf(fmaf(we, wv.x, hv.x) + bg.x, 0.f);
        acc.y += fmaxf(fmaf(we, wv.y, hv.y) + bg.y, 0.f);
        acc.z += fmaxf(fmaf(we, wv.z, hv.z) + bg.z, 0.f);
        acc.w += fmaxf(fmaf(we, wv.w, hv.w) + bg.w, 0.f);
    }
    st4(&aggr[node * HID_ + lane * 4], acc);
}

// ---------------------------------------------------------------------------
// Layer-0 node MLP (tensor core): 64 nodes/block, 4 warps x 16 rows.
// ---------------------------------------------------------------------------
__global__ void __launch_bounds__(128)
node_mlp16_tc(const float* __restrict__ xin, const float* __restrict__ aggr,
              const float* __restrict__ b1, const float* __restrict__ b2,
              float* __restrict__ hout)
{
    __shared__ __align__(16) float Z[64 * SSTR];

    int tid = threadIdx.x, w = tid >> 5, lane = tid & 31;
    int nb = blockIdx.x * 64;

    for (int i = tid; i < 64 * 4; i += 128) {
        int row = i >> 2, c4 = i & 3;
        int node = nb + row;
        float4 v = make_float4(0.f, 0.f, 0.f, 0.f);
        if (node < N_NODES_) {
            float4 a = ld4(&xin[node * NIN_ + c4 * 4]);
            float4 g = ld4(&aggr[node * NIN_ + c4 * 4]);
            v = make_float4(a.x + g.x, a.y + g.y, a.z + g.z, a.w + g.w);
        }
        st4(&Z[row * SSTR + c4 * 4], v);
    }
    __syncthreads();

    float c[16][4];
    const float* Zw = &Z[w * 16 * SSTR];
    int g = lane >> 2, t = lane & 3;

    mma_phase<2>(Zw, &g_WF[WF_W10], lane, c);
    __syncwarp();
    #pragma unroll
    for (int nt = 0; nt < 16; nt++) {
        int col = nt * 8 + 2 * t;
        float2 bb = *(const float2*)&b1[col];
        float2 e0 = make_float2(eluf(c[nt][0] + bb.x), eluf(c[nt][1] + bb.y));
        float2 e1 = make_float2(eluf(c[nt][2] + bb.x), eluf(c[nt][3] + bb.y));
        *(float2*)&Z[(w * 16 + g) * SSTR + col]     = e0;
        *(float2*)&Z[(w * 16 + g + 8) * SSTR + col] = e1;
    }
    __syncwarp();

    mma_phase<16>(Zw, &g_WF[WF_W20], lane, c);
    int n0 = nb + w * 16 + g;
    #pragma unroll
    for (int nt = 0; nt < 16; nt++) {
        int col = nt * 8 + 2 * t;
        float2 bb = *(const float2*)&b2[col];
        float2 e0 = make_float2(eluf(c[nt][0] + bb.x), eluf(c[nt][1] + bb.y));
        float2 e1 = make_float2(eluf(c[nt][2] + bb.x), eluf(c[nt][3] + bb.y));
        if (n0 < N_NODES_)     *(float2*)&hout[n0 * HID_ + col]       = e0;
        if (n0 + 8 < N_NODES_) *(float2*)&hout[(n0 + 8) * HID_ + col] = e1;
    }
}

// ---------------------------------------------------------------------------
// GINE MLP (tensor core): stage pre-aggregated rows, 2 MMA phases.
// ---------------------------------------------------------------------------
__global__ void __launch_bounds__(128)
gine_mma(const float* __restrict__ aggr,
         const uint4* __restrict__ WF1, const float* __restrict__ b1,
         const uint4* __restrict__ WF2, const float* __restrict__ b2,
         float* __restrict__ hout)
{
    __shared__ __align__(16) float Z[64 * SSTR];

    int tid = threadIdx.x, w = tid >> 5, lane = tid & 31;
    int nb = blockIdx.x * 64;

    for (int i = tid; i < 64 * 32; i += 128) {
        int row = i >> 5, c4 = i & 31;
        int node = nb + row;
        float4 v = make_float4(0.f, 0.f, 0.f, 0.f);
        if (node < N_NODES_) v = ld4(&aggr[node * HID_ + c4 * 4]);
        st4(&Z[row * SSTR + c4 * 4], v);
    }
    __syncthreads();

    float c[16][4];
    const float* Zw = &Z[w * 16 * SSTR];
    int g = lane >> 2, t = lane & 3;

    mma_phase<16>(Zw, WF1, lane, c);
    __syncwarp();
    #pragma unroll
    for (int nt = 0; nt < 16; nt++) {
        int col = nt * 8 + 2 * t;
        float2 bb = *(const float2*)&b1[col];
        float2 e0 = make_float2(eluf(c[nt][0] + bb.x), eluf(c[nt][1] + bb.y));
        float2 e1 = make_float2(eluf(c[nt][2] + bb.x), eluf(c[nt][3] + bb.y));
        *(float2*)&Z[(w * 16 + g) * SSTR + col]     = e0;
        *(float2*)&Z[(w * 16 + g + 8) * SSTR + col] = e1;
    }
    __syncwarp();

    mma_phase<16>(Zw, WF2, lane, c);
    int n0 = nb + w * 16 + g;
    #pragma unroll
    for (int nt = 0; nt < 16; nt++) {
        int col = nt * 8 + 2 * t;
        float2 bb = *(const float2*)&b2[col];
        float2 e0 = make_float2(eluf(c[nt][0] + bb.x), eluf(c[nt][1] + bb.y));
        float2 e1 = make_float2(eluf(c[nt][2] + bb.x), eluf(c[nt][3] + bb.y));
        if (n0 < N_NODES_)     *(float2*)&hout[n0 * HID_ + col]       = e0;
        if (n0 + 8 < N_NODES_) *(float2*)&hout[(n0 + 8) * HID_ + col] = e1;
    }
}

// ---------------------------------------------------------------------------
// Edge-predictor node factors. 64 nodes/block, 4 warps x 16 rows.
// ---------------------------------------------------------------------------
__global__ void __launch_bounds__(128)
k_prednode_tc(const float* __restrict__ h, float* __restrict__ P)
{
    __shared__ __align__(16) float Z[64 * SSTR];

    int tid = threadIdx.x, w = tid >> 5, lane = tid & 31;
    int nb = blockIdx.x * 64;

    for (int i = tid; i < 64 * 32; i += 128) {
        int row = i >> 5, c4 = i & 31;
        int node = nb + row;
        float4 v = make_float4(0.f, 0.f, 0.f, 0.f);
        if (node < N_NODES_) v = ld4(&h[node * HID_ + c4 * 4]);
        st4(&Z[row * SSTR + c4 * 4], v);
    }
    __syncthreads();

    float c[16][4];
    const float* Zw = &Z[w * 16 * SSTR];
    int g = lane >> 2, t = lane & 3;
    int n0 = nb + w * 16 + g;

    mma_phase<16>(Zw, &g_WF[WF_WPA], lane, c);
    #pragma unroll
    for (int nt = 0; nt < 16; nt++) {
        int col = nt * 8 + 2 * t;
        if (n0 < N_NODES_)     *(float2*)&P[n0 * 256 + col]       = make_float2(c[nt][0], c[nt][1]);
        if (n0 + 8 < N_NODES_) *(float2*)&P[(n0 + 8) * 256 + col] = make_float2(c[nt][2], c[nt][3]);
    }

    mma_phase<16>(Zw, &g_WF[WF_WPB], lane, c);
    #pragma unroll
    for (int nt = 0; nt < 16; nt++) {
        int col = nt * 8 + 2 * t;
        if (n0 < N_NODES_)     *(float2*)&P[n0 * 256 + 128 + col]       = make_float2(c[nt][0], c[nt][1]);
        if (n0 + 8 < N_NODES_) *(float2*)&P[(n0 + 8) * 256 + 128 + col] = make_float2(c[nt][2], c[nt][3]);
    }
}

// ---------------------------------------------------------------------------
// Per-edge predictor epilogue: out[e] = elu(A[src]+B[dst]+bp1) . Wp2 + bp2
// ---------------------------------------------------------------------------
__global__ void k_prededge(const float* __restrict__ P, const int* __restrict__ ei,
                           const float* __restrict__ bp1, const float* __restrict__ Wp2,
                           const float* __restrict__ bp2, float* __restrict__ out)
{
    int warp = (blockIdx.x * blockDim.x + threadIdx.x) >> 5;
    int lane = threadIdx.x & 31;
    int e0 = warp * 4;
    if (e0 >= N_EDGES_) return;

    float4 bv = ld4(&bp1[lane * 4]);
    float4 w2 = ld4(&Wp2[lane * 4]);
    float cc = bp2[0];

    #pragma unroll
    for (int n = 0; n < 4; n++) {
        int e = e0 + n;
        int src = ei[e];
        int dst = ei[N_EDGES_ + e];
        float4 a = ld4(&P[src * 256 + lane * 4]);
        float4 b = ld4(&P[dst * 256 + 128 + lane * 4]);
        float4 tt;
        tt.x = eluf(a.x + b.x + bv.x);
        tt.y = eluf(a.y + b.y + bv.y);
        tt.z = eluf(a.z + b.z + bv.z);
        tt.w = eluf(a.w + b.w + bv.w);
        float p = tt.x * w2.x + tt.y * w2.y + tt.z * w2.z + tt.w * w2.w;
        #pragma unroll
        for (int off = 16; off; off >>= 1)
            p += __shfl_xor_sync(0xffffffffu, p, off);
        if (lane == 0) out[e] = p + cc;
    }
}

// ---------------------------------------------------------------------------
extern "C" void kernel_launch(void* const* d_in, const int* in_sizes, int n_in,
                              void* d_out, int out_size)
{
    const float* x    = (const float*)d_in[0];
    const int*   ei   = (const int*)  d_in[1];
    const float* ea   = (const float*)d_in[2];
    const float* We0  = (const float*)d_in[3];
    const float* be0  = (const float*)d_in[4];
    const float* W10  = (const float*)d_in[5];
    const float* b10  = (const float*)d_in[6];
    const float* W20  = (const float*)d_in[7];
    const float* b20  = (const float*)d_in[8];
    const float* We_s = (const float*)d_in[9];
    const float* be_s = (const float*)d_in[10];
    const float* W1_s = (const float*)d_in[11];
    const float* b1_s = (const float*)d_in[12];
    const float* W2_s = (const float*)d_in[13];
    const float* b2_s = (const float*)d_in[14];
    const float* Wp1  = (const float*)d_in[15];
    const float* bp1  = (const float*)d_in[16];
    const float* Wp2  = (const float*)d_in[17];
    const float* bp2  = (const float*)d_in[18];
    float* out = (float*)d_out;

    float *hA, *hB, *P;
    uint4* WF;
    int *deg;
    cudaGetSymbolAddress((void**)&hA, g_h);
    cudaGetSymbolAddress((void**)&hB, g_hn);
    cudaGetSymbolAddress((void**)&P,  g_P);
    cudaGetSymbolAddress((void**)&WF, g_WF);
    cudaGetSymbolAddress((void**)&deg, g_deg);

    // ---- weight fragment prep + CSR build ----
    k_wfrag<<<(WF_TOTAL + 255) / 256, 256>>>(W10, W20, W1_s, W2_s, Wp1);
    cudaMemsetAsync(deg, 0, N_NODES_ * sizeof(int));
    k_hist <<<(N_EDGES_ + 255) / 256, 256>>>(ei);
    k_scanA<<<NBLK_, SCAN_B>>>();
    k_scanB<<<1, 128>>>();
    k_scanC<<<NBLK_, SCAN_B>>>();
    k_fill <<<(N_EDGES_ + 255) / 256, 256>>>(ei, ea);

    // ---- Layer 0 (16 -> 128) ----
    k_aggr0<<<(N_NODES_ * 16 + 255) / 256, 256>>>(x, We0, be0, P);   // reuse P as aggr16
    node_mlp16_tc<<<NODE_BLKS, 128>>>(x, P, b10, b20, hA);

    // ---- Layers 1..4: warp-per-node aggregation, then pure-MMA MLP ----
    for (int l = 0; l < 4; l++) {
        k_aggr_hid<<<(N_NODES_ * 32 + 255) / 256, 256>>>(hA,
                                                         We_s + l * HID_, be_s + l * HID_, P);
        gine_mma<<<NODE_BLKS, 128>>>(P,
                                     WF + WF_W1 + l * 8192, b1_s + l * HID_,
                                     WF + WF_W2 + l * 8192, b2_s + l * HID_, hB);
        float* t = hA; hA = hB; hB = t;
    }

    // ---- Edge predictor ----
    k_prednode_tc<<<NODE_BLKS, 128>>>(hA, P);
    k_prededge<<<(N_EDGES_ / 4 * 32 + 255) / 256, 256>>>(P, ei, bp1, Wp2, bp2, out);
}